// round 16
// baseline (speedup 1.0000x reference)
#include <cuda_runtime.h>
#include <cuda_fp16.h>
#include <cstdint>

// ---------------- problem constants ----------------
#define DEGREE   3
#define NB       7
#define NKNOTS   11
#define BATCH    8192
#define IN_DIM   1024
#define OUT_DIM  1024
#define KDIM     (IN_DIM * 8)   // 8192: 7 basis cols + 1 linear col per input

// Fused GEMM: 64x256 CTA tile, 8 warps (2Mx4N) of the proven 32x64 warp tile,
// 2-stage pipeline (wait -> sync -> [compute + in-kernel A-basis] -> sync ->
// [STS A + cp.async B]). A is never materialized in DRAM: each CTA computes the
// basis for its 64x64k A-slab from precomputed t=tanh(x) (fp32) using idle
// issue/FMA slots under the 2048-cyc tensor window. 83KB smem -> 2 CTAs/SM.
#define BM 64
#define BN 256
#define BK 64
#define KITERS (KDIM / BK)      // 128
#define THREADS 256

#define A_STAGE (BM * BK * 2)   // 8192 B  (64 rows x 128B)
#define B_STAGE (BN * BK * 2)   // 32768 B (256 rows x 128B)
#define A_OFF 0
#define B_OFF (2 * A_STAGE)                        // 16384
#define SMEM_BYTES (B_OFF + 2 * B_STAGE + 1024)    // 81920 + align slack

// prep grid split
#define A_BLOCKS 8192            // t/x16 build: 8192 blocks x 256 thr x 4 elems
#define B_TI 16
#define B_TO 32
#define B_BLOCKS ((IN_DIM / B_TI) * (OUT_DIM / B_TO))  // 2048

// ---------------- scratch (device globals; no cudaMalloc allowed) ----------------
__device__ float  g_t[(size_t)BATCH * IN_DIM];    // 32 MB  tanh(x), fp32
__device__ __half g_x16[(size_t)BATCH * IN_DIM];  // 16 MB  x, fp16
__device__ __half g_B[(size_t)OUT_DIM * KDIM];    // 16 MB

// ---------------- PTX helpers (baseline ISA only) ----------------
__device__ __forceinline__ uint32_t smem_u32(const void* p) {
    uint32_t a;
    asm("{ .reg .u64 t; cvta.to.shared.u64 t, %1; cvt.u32.u64 %0, t; }" : "=r"(a) : "l"(p));
    return a;
}
__device__ __forceinline__ void cp_async16(uint32_t sdst, const void* gsrc) {
    asm volatile("cp.async.cg.shared.global [%0], [%1], 16;" :: "r"(sdst), "l"(gsrc));
}
#define CP_COMMIT() asm volatile("cp.async.commit_group;" ::: "memory")
#define CP_WAIT(n)  asm volatile("cp.async.wait_group %0;" :: "n"(n) : "memory")

#define LDSM_X4(r0, r1, r2, r3, addr) \
    asm volatile("ldmatrix.sync.aligned.m8n8.x4.shared.b16 {%0,%1,%2,%3}, [%4];" \
                 : "=r"(r0), "=r"(r1), "=r"(r2), "=r"(r3) : "r"(addr))

#define MMA16816(d, a, b0v, b1v) \
    asm volatile("mma.sync.aligned.m16n8k16.row.col.f32.f16.f16.f32 " \
                 "{%0,%1,%2,%3}, {%4,%5,%6,%7}, {%8,%9}, {%0,%1,%2,%3};" \
                 : "+f"((d)[0]), "+f"((d)[1]), "+f"((d)[2]), "+f"((d)[3]) \
                 : "r"((a)[0]), "r"((a)[1]), "r"((a)[2]), "r"((a)[3]), \
                   "r"(b0v), "r"(b1v))

// ---------------- basis from precomputed fp32 t ----------------
// Indicators: s_j = (t - kn_j >= 0) == (t >= kn_j) bit-exactly in fp32 (the
// difference is never subnormal at knot magnitudes), so truncated-basis
// discontinuities match the reference. Recurrence factored: u_j = t - kn_j,
// bas_j <- fma(u_j, bas_j, -u_{j+d+1}*bas_{j+1}); uniform-knot constants
// deferred to one final scale 125/6 (continuous ~1-ulp reassociation).
// Clamp dropped: prep's tanh saturates to exactly +-1 = kn0/kn10.
__device__ __forceinline__ void basis_pack(float t, uint16_t xh,
                                           const float* __restrict__ ks,
                                           uint32_t* p) {
    float u[NKNOTS];
#pragma unroll
    for (int j = 0; j < NKNOTS; ++j) u[j] = t - ks[j];
    float bas[NB];
#pragma unroll
    for (int j = 0; j < NB; ++j) {
        float sj  = (u[j]     >= 0.0f) ? 1.0f : 0.0f;
        float sj1 = (u[j + 1] >= 0.0f) ? 1.0f : 0.0f;
        bas[j] = sj - sj1;
    }
#pragma unroll
    for (int d = 1; d <= DEGREE; ++d) {
#pragma unroll
        for (int j = 0; j < NB; ++j) {
            float nxt = (j + 1 < NB) ? bas[j + 1] : 0.0f;
            bas[j] = __fmaf_rn(u[j], bas[j], -u[j + d + 1] * nxt);
        }
    }
    const float KS = 125.0f / 6.0f;
#pragma unroll
    for (int j = 0; j < NB; ++j) bas[j] *= KS;

    __half2 p0 = __floats2half2_rn(bas[0], bas[1]);
    __half2 p1 = __floats2half2_rn(bas[2], bas[3]);
    __half2 p2 = __floats2half2_rn(bas[4], bas[5]);
    p[0] = *reinterpret_cast<uint32_t*>(&p0);
    p[1] = *reinterpret_cast<uint32_t*>(&p1);
    p[2] = *reinterpret_cast<uint32_t*>(&p2);
    p[3] = (uint32_t)__half_as_ushort(__float2half_rn(bas[6])) | ((uint32_t)xh << 16);
}

// ---------------- merged prep kernel (t/x16 build + B build) ----------------
__global__ void __launch_bounds__(256) build_prep_kernel(
    const float* __restrict__ x, const float* __restrict__ sw,
    const float* __restrict__ W)
{
    __shared__ float sw_s[B_TI * 225];      // 16 rows x (224, pad 225)
    __shared__ float w_s[B_TO * 17];        // 32 x 16 (+pad)

    const int tid = threadIdx.x;
    if (blockIdx.x < A_BLOCKS) {
        int base = (blockIdx.x * 256 + tid) * 4;
        float4 xv = *reinterpret_cast<const float4*>(x + base);
        float4 tv;
        {   // fast tanh: 1 - 2/(exp(2x)+1); exact saturation at +-1
            float e0 = __expf(2.0f * xv.x), e1 = __expf(2.0f * xv.y);
            float e2 = __expf(2.0f * xv.z), e3 = __expf(2.0f * xv.w);
            tv.x = 1.0f - __fdividef(2.0f, e0 + 1.0f);
            tv.y = 1.0f - __fdividef(2.0f, e1 + 1.0f);
            tv.z = 1.0f - __fdividef(2.0f, e2 + 1.0f);
            tv.w = 1.0f - __fdividef(2.0f, e3 + 1.0f);
        }
        *reinterpret_cast<float4*>(g_t + base) = tv;
        __half2 h0 = __floats2half2_rn(xv.x, xv.y);
        __half2 h1 = __floats2half2_rn(xv.z, xv.w);
        uint2 hx = {*reinterpret_cast<uint32_t*>(&h0), *reinterpret_cast<uint32_t*>(&h1)};
        *reinterpret_cast<uint2*>(g_x16 + base) = hx;
        return;
    }

    // ---- B part: smem-tiled transpose of spline weights + W ----
    const int bid = blockIdx.x - A_BLOCKS;
    const int i0 = (bid & 63) * B_TI;
    const int o0 = (bid >> 6) * B_TO;

#pragma unroll
    for (int j = 0; j < 14; ++j) {
        int f = tid + j * 256;               // < 3584
        int r = f / 224, c = f % 224;
        sw_s[r * 225 + c] = __ldg(&sw[((size_t)(i0 + r) * OUT_DIM + o0) * NB + c]);
    }
#pragma unroll
    for (int j = 0; j < 2; ++j) {
        int f = tid + j * 256;               // < 512
        int r = f >> 4, c = f & 15;
        w_s[r * 17 + c] = __ldg(&W[(size_t)(o0 + r) * IN_DIM + i0 + c]);
    }
    __syncthreads();

#pragma unroll
    for (int p = 0; p < 2; ++p) {
        int o = (tid >> 4) + p * 16;
        int il = tid & 15;
        __half h[8];
#pragma unroll
        for (int k = 0; k < NB; ++k)
            h[k] = __float2half_rn(sw_s[il * 225 + o * 7 + k]);
        h[7] = __float2half_rn(w_s[o * 17 + il]);
        *reinterpret_cast<uint4*>(&g_B[(size_t)(o0 + o) * KDIM + (size_t)(i0 + il) * 8]) =
            *reinterpret_cast<const uint4*>(h);
    }
}

// ---------------- fused GEMM: out = [basis(t) | x] * [sw | W]^T + bias ----------------
__global__ void __launch_bounds__(THREADS, 2)
kan_gemm_kernel(float* __restrict__ out, const float* __restrict__ bias,
                const float* __restrict__ knots) {
    extern __shared__ char smem_raw[];
    __shared__ float ksm[16];
    char* SB = smem_raw +
        ((1024 - ((uintptr_t)smem_raw & 1023)) & 1023);   // 1024-aligned base
    const uint32_t S = smem_u32(SB);

    const int tid  = threadIdx.x;
    const int wid  = tid >> 5;
    const int lane = tid & 31;
    const int wm   = wid >> 2;      // 0..1  (M halves)
    const int wn   = wid & 3;       // 0..3  (N quarters)
    const int n0 = blockIdx.x * BN;
    const int m0 = blockIdx.y * BM;

    const __half* gB = g_B + (size_t)n0 * KDIM;

    // per-thread A-element pair: row = tid>>2 (0..63), cols cc2, cc2+1 (0..7)
    const int arow = tid >> 2;
    const int cc2  = (tid & 3) * 2;
    const float*  tptr = g_t   + (size_t)(m0 + arow) * IN_DIM + cc2;
    const __half* xptr = g_x16 + (size_t)(m0 + arow) * IN_DIM + cc2;
    const uint32_t aoff0 = (uint32_t)(arow * 128 + ((cc2 * 16) ^ ((arow & 7) * 16)));
    const uint32_t aoff1 = (uint32_t)(arow * 128 + (((cc2 + 1) * 16) ^ ((arow & 7) * 16)));

    auto load_B_stage = [&](int it, int buf) {
        const int k0 = it * BK;
        const uint32_t bb = S + B_OFF + buf * B_STAGE;
#pragma unroll
        for (int t = 0; t < 8; ++t) {               // B: 2048 chunks of 16B
            int ch = tid + t * THREADS;
            int row = ch >> 3, cc = ch & 7;
            cp_async16(bb + row * 128 + ((cc * 16) ^ ((row & 7) * 16)),
                       gB + (size_t)row * KDIM + k0 + cc * 8);
        }
        CP_COMMIT();
    };

    auto sts_pack = [&](int buf, const uint32_t* p) {
        char* ab = SB + A_OFF + buf * A_STAGE;
        *reinterpret_cast<uint4*>(ab + aoff0) = make_uint4(p[0], p[1], p[2], p[3]);
        *reinterpret_cast<uint4*>(ab + aoff1) = make_uint4(p[4], p[5], p[6], p[7]);
    };

    // ---- prologue ----
    load_B_stage(0, 0);
    load_B_stage(1, 1);
    if (tid < NKNOTS) ksm[tid] = __ldg(&knots[tid]);
    __syncthreads();                       // ksm visible

    {
        uint32_t pk[8];
#pragma unroll
        for (int s = 0; s < 2; ++s) {
            float2 tp = *reinterpret_cast<const float2*>(tptr + s * 8);
            uint32_t xp = *reinterpret_cast<const uint32_t*>(xptr + s * 8);
            basis_pack(tp.x, (uint16_t)(xp & 0xFFFF), ksm, pk);
            basis_pack(tp.y, (uint16_t)(xp >> 16),    ksm, pk + 4);
            sts_pack(s, pk);
        }
    }
    // prefetch stage 2 t/x
    float2   tpre = *reinterpret_cast<const float2*>(tptr + 2 * 8);
    uint32_t xpre = *reinterpret_cast<const uint32_t*>(xptr + 2 * 8);

    // ---- per-lane ldmatrix addressing (proven 32x64 warp tile) ----
    uint32_t aRow[2], aXor[2];
#pragma unroll
    for (int mi = 0; mi < 2; ++mi) {
        int row = wm * 32 + mi * 16 + (lane & 15);
        aRow[mi] = (uint32_t)(row * 128);
        aXor[mi] = (uint32_t)((row & 7) * 16);
    }
    const uint32_t aK = ((lane >> 4) * 16);

    uint32_t bRow[4], bXor[4];
#pragma unroll
    for (int g = 0; g < 4; ++g) {
        int row = wn * 64 + g * 16 + ((lane >> 4) << 3) + (lane & 7);
        bRow[g] = (uint32_t)(row * 128);
        bXor[g] = (uint32_t)((row & 7) * 16);
    }
    const uint32_t bK = (((lane >> 3) & 1) * 16);

    float acc[2][8][4];
#pragma unroll
    for (int mi = 0; mi < 2; ++mi)
#pragma unroll
        for (int ni = 0; ni < 8; ++ni)
#pragma unroll
            for (int r = 0; r < 4; ++r) acc[mi][ni][r] = 0.0f;

    // ---- mainloop ----
    for (int it = 0; it < KITERS; ++it) {
        const int buf = it & 1;
        if (it == KITERS - 1) { CP_WAIT(0); } else { CP_WAIT(1); }
        __syncthreads();

        // basis for stage it+2 from regs prefetched last iter (idle FMA slots)
        uint32_t pk[8];
        const bool havenext = (it + 2 < KITERS);
        if (havenext) {
            basis_pack(tpre.x, (uint16_t)(xpre & 0xFFFF), ksm, pk);
            basis_pack(tpre.y, (uint16_t)(xpre >> 16),    ksm, pk + 4);
        }
        if (it + 3 < KITERS) {             // prefetch stage it+3
            tpre = *reinterpret_cast<const float2*>(tptr + (size_t)(it + 3) * 8);
            xpre = *reinterpret_cast<const uint32_t*>(xptr + (size_t)(it + 3) * 8);
        }

        const uint32_t abase = S + A_OFF + buf * A_STAGE;
        const uint32_t bbase = S + B_OFF + buf * B_STAGE;
#pragma unroll
        for (int kk = 0; kk < 4; ++kk) {
            uint32_t a[2][4];
#pragma unroll
            for (int mi = 0; mi < 2; ++mi)
                LDSM_X4(a[mi][0], a[mi][1], a[mi][2], a[mi][3],
                        abase + aRow[mi] + (((uint32_t)(kk * 32) + aK) ^ aXor[mi]));
            uint32_t b[4][4];
#pragma unroll
            for (int g = 0; g < 4; ++g)
                LDSM_X4(b[g][0], b[g][1], b[g][2], b[g][3],
                        bbase + bRow[g] + (((uint32_t)(kk * 32) + bK) ^ bXor[g]));
#pragma unroll
            for (int mi = 0; mi < 2; ++mi)
#pragma unroll
                for (int g = 0; g < 4; ++g) {
                    MMA16816(acc[mi][2 * g + 0], a[mi], b[g][0], b[g][1]);
                    MMA16816(acc[mi][2 * g + 1], a[mi], b[g][2], b[g][3]);
                }
        }

        if (havenext) {
            __syncthreads();               // all warps done reading buf (WAR)
            sts_pack(buf, pk);             // A(it+2)
            load_B_stage(it + 2, buf);     // B(it+2)
        }
    }

    // ---- epilogue ----
    const int r  = lane >> 2;
    const int c2 = (lane & 3) * 2;
    float bia[8][2];
#pragma unroll
    for (int ni = 0; ni < 8; ++ni) {
        bia[ni][0] = __ldg(&bias[n0 + wn * 64 + ni * 8 + c2 + 0]);
        bia[ni][1] = __ldg(&bias[n0 + wn * 64 + ni * 8 + c2 + 1]);
    }
#pragma unroll
    for (int mi = 0; mi < 2; ++mi) {
        const int mrow = m0 + wm * 32 + mi * 16 + r;
        float* o0 = out + (size_t)mrow * OUT_DIM + n0 + wn * 64;
        float* o1 = o0 + 8 * OUT_DIM;
#pragma unroll
        for (int ni = 0; ni < 8; ++ni) {
            const int nc = ni * 8 + c2;
            float2 v0 = {acc[mi][ni][0] + bia[ni][0], acc[mi][ni][1] + bia[ni][1]};
            float2 v1 = {acc[mi][ni][2] + bia[ni][0], acc[mi][ni][3] + bia[ni][1]};
            *reinterpret_cast<float2*>(o0 + nc) = v0;
            *reinterpret_cast<float2*>(o1 + nc) = v1;
        }
    }
}

// ---------------- launch ----------------
extern "C" void kernel_launch(void* const* d_in, const int* in_sizes, int n_in,
                              void* d_out, int out_size) {
    const float* x     = (const float*)d_in[0];
    const float* sw    = (const float*)d_in[1];
    const float* W     = (const float*)d_in[2];
    const float* bias  = (const float*)d_in[3];
    const float* knots = (const float*)d_in[4];
    float* out = (float*)d_out;

    build_prep_kernel<<<A_BLOCKS + B_BLOCKS, 256>>>(x, sw, W);

    cudaFuncSetAttribute(kan_gemm_kernel, cudaFuncAttributeMaxDynamicSharedMemorySize, SMEM_BYTES);
    dim3 grid(OUT_DIM / BN, BATCH / BM);   // (4, 128) = 512 CTAs
    kan_gemm_kernel<<<grid, THREADS, SMEM_BYTES>>>(out, bias, knots);
}

// round 17
// speedup vs baseline: 1.0128x; 1.0128x over previous
#include <cuda_runtime.h>
#include <cuda_fp16.h>
#include <cstdint>

// ---------------- problem constants ----------------
#define DEGREE   3
#define NB       7
#define NKNOTS   11
#define BATCH    8192
#define IN_DIM   1024
#define OUT_DIM  1024
#define KDIM     (IN_DIM * 8)   // 8192: 7 basis cols + 1 linear col per input

// Warp-specialized fused GEMM: 64x128 CTA tile, 256 threads.
// Warps 0-3: pure MMA (proven R10 32x64 warp tiles, ~124 regs, no LSU work).
// Warps 4-7: producers — compute the B-spline basis in-register from fp32
//   t=tanh(x), STS the A tile, cp.async the B tile, own all CP_WAITs.
// g_A (128MB write + 128MB read) is never materialized: prep shrinks to
// t/x16/B builds (~64MB). 48KB smem, 2 CTA/SM -> 16 warps/SM (as R10).
#define BM 64
#define BN 128
#define BK 64
#define KITERS (KDIM / BK)      // 128
#define THREADS 256

#define A_STAGE (BM * BK * 2)   // 8192 B  (64 rows x 128B)
#define B_STAGE (BN * BK * 2)   // 16384 B (128 rows x 128B)
#define A_OFF 0
#define B_OFF (2 * A_STAGE)                        // 16384
#define SMEM_BYTES (B_OFF + 2 * B_STAGE + 1024)    // 49152 + align slack

// prep grid split
#define A_BLOCKS 8192            // t/x16 build: 8192 blocks x 256 thr x 4 elems
#define B_TI 16
#define B_TO 32
#define B_BLOCKS ((IN_DIM / B_TI) * (OUT_DIM / B_TO))  // 2048

// ---------------- scratch (device globals; no cudaMalloc allowed) ----------------
__device__ float  g_t[(size_t)BATCH * IN_DIM];    // 32 MB  tanh(x), fp32
__device__ __half g_x16[(size_t)BATCH * IN_DIM];  // 16 MB  x, fp16
__device__ __half g_B[(size_t)OUT_DIM * KDIM];    // 16 MB

// ---------------- PTX helpers (baseline ISA only) ----------------
__device__ __forceinline__ uint32_t smem_u32(const void* p) {
    uint32_t a;
    asm("{ .reg .u64 t; cvta.to.shared.u64 t, %1; cvt.u32.u64 %0, t; }" : "=r"(a) : "l"(p));
    return a;
}
__device__ __forceinline__ void cp_async16(uint32_t sdst, const void* gsrc) {
    asm volatile("cp.async.cg.shared.global [%0], [%1], 16;" :: "r"(sdst), "l"(gsrc));
}
#define CP_COMMIT() asm volatile("cp.async.commit_group;" ::: "memory")
#define CP_WAIT(n)  asm volatile("cp.async.wait_group %0;" :: "n"(n) : "memory")

#define LDSM_X4(r0, r1, r2, r3, addr) \
    asm volatile("ldmatrix.sync.aligned.m8n8.x4.shared.b16 {%0,%1,%2,%3}, [%4];" \
                 : "=r"(r0), "=r"(r1), "=r"(r2), "=r"(r3) : "r"(addr))

#define MMA16816(d, a, b0v, b1v) \
    asm volatile("mma.sync.aligned.m16n8k16.row.col.f32.f16.f16.f32 " \
                 "{%0,%1,%2,%3}, {%4,%5,%6,%7}, {%8,%9}, {%0,%1,%2,%3};" \
                 : "+f"((d)[0]), "+f"((d)[1]), "+f"((d)[2]), "+f"((d)[3]) \
                 : "r"((a)[0]), "r"((a)[1]), "r"((a)[2]), "r"((a)[3]), \
                   "r"(b0v), "r"(b1v))

// ---------------- basis from precomputed fp32 t ----------------
// Indicators: s_j = (t - kn_j >= 0) == (t >= kn_j) bit-exactly in fp32, so the
// truncated-basis discontinuities match the reference. Recurrence factored:
// u_j = t - kn_j; bas_j <- fma(u_j, bas_j, -u_{j+d+1}*bas_{j+1}); uniform-knot
// constants deferred to one final scale 125/6 (continuous ~1-ulp reassociation).
// Clamp dropped: prep's tanh saturates to exactly +-1 = kn0/kn10.
__device__ __forceinline__ void basis_pack(float t, uint16_t xh,
                                           const float* __restrict__ ks,
                                           uint32_t* p) {
    float u[NKNOTS];
#pragma unroll
    for (int j = 0; j < NKNOTS; ++j) u[j] = t - ks[j];
    float bas[NB];
#pragma unroll
    for (int j = 0; j < NB; ++j) {
        float sj  = (u[j]     >= 0.0f) ? 1.0f : 0.0f;
        float sj1 = (u[j + 1] >= 0.0f) ? 1.0f : 0.0f;
        bas[j] = sj - sj1;
    }
#pragma unroll
    for (int d = 1; d <= DEGREE; ++d) {
#pragma unroll
        for (int j = 0; j < NB; ++j) {
            float nxt = (j + 1 < NB) ? bas[j + 1] : 0.0f;
            bas[j] = __fmaf_rn(u[j], bas[j], -u[j + d + 1] * nxt);
        }
    }
    const float KS = 125.0f / 6.0f;
#pragma unroll
    for (int j = 0; j < NB; ++j) bas[j] *= KS;

    __half2 p0 = __floats2half2_rn(bas[0], bas[1]);
    __half2 p1 = __floats2half2_rn(bas[2], bas[3]);
    __half2 p2 = __floats2half2_rn(bas[4], bas[5]);
    p[0] = *reinterpret_cast<uint32_t*>(&p0);
    p[1] = *reinterpret_cast<uint32_t*>(&p1);
    p[2] = *reinterpret_cast<uint32_t*>(&p2);
    p[3] = (uint32_t)__half_as_ushort(__float2half_rn(bas[6])) | ((uint32_t)xh << 16);
}

// ---------------- merged prep kernel (t/x16 build + B build) ----------------
__global__ void __launch_bounds__(256) build_prep_kernel(
    const float* __restrict__ x, const float* __restrict__ sw,
    const float* __restrict__ W)
{
    __shared__ float sw_s[B_TI * 225];      // 16 rows x (224, pad 225)
    __shared__ float w_s[B_TO * 17];        // 32 x 16 (+pad)

    const int tid = threadIdx.x;
    if (blockIdx.x < A_BLOCKS) {
        int base = (blockIdx.x * 256 + tid) * 4;
        float4 xv = *reinterpret_cast<const float4*>(x + base);
        float4 tv;
        {   // fast tanh: 1 - 2/(exp(2x)+1); exact saturation at +-1
            float e0 = __expf(2.0f * xv.x), e1 = __expf(2.0f * xv.y);
            float e2 = __expf(2.0f * xv.z), e3 = __expf(2.0f * xv.w);
            tv.x = 1.0f - __fdividef(2.0f, e0 + 1.0f);
            tv.y = 1.0f - __fdividef(2.0f, e1 + 1.0f);
            tv.z = 1.0f - __fdividef(2.0f, e2 + 1.0f);
            tv.w = 1.0f - __fdividef(2.0f, e3 + 1.0f);
        }
        *reinterpret_cast<float4*>(g_t + base) = tv;
        __half2 h0 = __floats2half2_rn(xv.x, xv.y);
        __half2 h1 = __floats2half2_rn(xv.z, xv.w);
        uint2 hx = {*reinterpret_cast<uint32_t*>(&h0), *reinterpret_cast<uint32_t*>(&h1)};
        *reinterpret_cast<uint2*>(g_x16 + base) = hx;
        return;
    }

    // ---- B part: smem-tiled transpose of spline weights + W ----
    const int bid = blockIdx.x - A_BLOCKS;
    const int i0 = (bid & 63) * B_TI;
    const int o0 = (bid >> 6) * B_TO;

#pragma unroll
    for (int j = 0; j < 14; ++j) {
        int f = tid + j * 256;               // < 3584
        int r = f / 224, c = f % 224;
        sw_s[r * 225 + c] = __ldg(&sw[((size_t)(i0 + r) * OUT_DIM + o0) * NB + c]);
    }
#pragma unroll
    for (int j = 0; j < 2; ++j) {
        int f = tid + j * 256;               // < 512
        int r = f >> 4, c = f & 15;
        w_s[r * 17 + c] = __ldg(&W[(size_t)(o0 + r) * IN_DIM + i0 + c]);
    }
    __syncthreads();

#pragma unroll
    for (int p = 0; p < 2; ++p) {
        int o = (tid >> 4) + p * 16;
        int il = tid & 15;
        __half h[8];
#pragma unroll
        for (int k = 0; k < NB; ++k)
            h[k] = __float2half_rn(sw_s[il * 225 + o * 7 + k]);
        h[7] = __float2half_rn(w_s[o * 17 + il]);
        *reinterpret_cast<uint4*>(&g_B[(size_t)(o0 + o) * KDIM + (size_t)(i0 + il) * 8]) =
            *reinterpret_cast<const uint4*>(h);
    }
}

// ---------------- warp-specialized fused GEMM ----------------
// Barrier protocol per iter (both paths execute the SAME count):
//   barrier1 (always), barrier2 iff it+2 < KITERS.
// Producers: CP_WAIT before barrier1; after barrier2 they STS A(it+2)
// (WAR-safe: MMA warps just finished reading buf) + cp.async B(it+2) +
// prefetch t/x(it+3). MMA warps: pure LDSM+MMA between the barriers.
__global__ void __launch_bounds__(THREADS, 2)
kan_gemm_kernel(float* __restrict__ out, const float* __restrict__ bias,
                const float* __restrict__ knots) {
    extern __shared__ char smem_raw[];
    char* SB = smem_raw +
        ((1024 - ((uintptr_t)smem_raw & 1023)) & 1023);   // 1024-aligned base
    const uint32_t S = smem_u32(SB);

    const int tid  = threadIdx.x;
    const int wid  = tid >> 5;
    const int lane = tid & 31;
    const int n0 = blockIdx.x * BN;
    const int m0 = blockIdx.y * BM;

    const __half* gB = g_B + (size_t)n0 * KDIM;

    if (wid >= 4) {
        // ================= producer warps (4-7) =================
        const int ptid = tid - 128;              // 0..127
        const int cc    = ptid & 7;              // i-offset within stage
        const int rbase = ptid >> 3;             // 0..15; rows rbase+16j
        const uint32_t csw = ((uint32_t)(cc * 16)) ^ ((uint32_t)((rbase & 7) * 16));
        uint32_t aoff[4];
#pragma unroll
        for (int j = 0; j < 4; ++j)
            aoff[j] = (uint32_t)((rbase + 16 * j) * 128) + csw;
        const float*  tb = g_t   + (size_t)(m0 + rbase) * IN_DIM + cc;
        const __half* xb = g_x16 + (size_t)(m0 + rbase) * IN_DIM + cc;

        float kn[NKNOTS];
#pragma unroll
        for (int j = 0; j < NKNOTS; ++j) kn[j] = __ldg(&knots[j]);

        auto load_B = [&](int it, int buf) {
            const int k0 = it * BK;
            const uint32_t bb = S + B_OFF + buf * B_STAGE;
#pragma unroll
            for (int t = 0; t < 8; ++t) {        // 1024 chunks / 128 thr
                int ch = ptid + t * 128;
                int row = ch >> 3, c = ch & 7;
                cp_async16(bb + row * 128 + ((c * 16) ^ ((row & 7) * 16)),
                           gB + (size_t)row * KDIM + k0 + c * 8);
            }
            CP_COMMIT();
        };
        load_B(0, 0);
        load_B(1, 1);

        // A stages 0,1 (i index for stage s, chunk cc is s*8+cc -> col offset s*8)
#pragma unroll
        for (int s = 0; s < 2; ++s) {
#pragma unroll
            for (int j = 0; j < 4; ++j) {
                float tv = __ldg(tb + (size_t)(16 * j) * IN_DIM + s * 8);
                uint16_t xh = __half_as_ushort(__ldg(xb + (size_t)(16 * j) * IN_DIM + s * 8));
                uint32_t pk[4];
                basis_pack(tv, xh, kn, pk);
                *reinterpret_cast<uint4*>(SB + A_OFF + s * A_STAGE + aoff[j]) =
                    make_uint4(pk[0], pk[1], pk[2], pk[3]);
            }
        }
        float tn[4]; uint16_t xn[4];
#pragma unroll
        for (int j = 0; j < 4; ++j) {
            tn[j] = __ldg(tb + (size_t)(16 * j) * IN_DIM + 2 * 8);
            xn[j] = __half_as_ushort(__ldg(xb + (size_t)(16 * j) * IN_DIM + 2 * 8));
        }

        for (int it = 0; it < KITERS; ++it) {
            const int buf = it & 1;
            if (it == KITERS - 1) { CP_WAIT(0); } else { CP_WAIT(1); }
            __syncthreads();                     // barrier 1
            if (it + 2 < KITERS) {
                __syncthreads();                 // barrier 2 (MMA done reading buf)
#pragma unroll
                for (int j = 0; j < 4; ++j) {    // A(it+2) -> buf
                    uint32_t pk[4];
                    basis_pack(tn[j], xn[j], kn, pk);
                    *reinterpret_cast<uint4*>(SB + A_OFF + buf * A_STAGE + aoff[j]) =
                        make_uint4(pk[0], pk[1], pk[2], pk[3]);
                }
                load_B(it + 2, buf);             // B(it+2)
                if (it + 3 < KITERS) {
#pragma unroll
                    for (int j = 0; j < 4; ++j) {
                        tn[j] = __ldg(tb + (size_t)(16 * j) * IN_DIM + (size_t)(it + 3) * 8);
                        xn[j] = __half_as_ushort(
                            __ldg(xb + (size_t)(16 * j) * IN_DIM + (size_t)(it + 3) * 8));
                    }
                }
            }
        }
        return;  // producers exit; no further barriers in MMA path
    }

    // ================= MMA warps (0-3): proven R10 32x64 warp tiles =================
    const int wm = wid >> 1;      // 0..1
    const int wn = wid & 1;       // 0..1

    uint32_t aRow[2], aXor[2];
#pragma unroll
    for (int mi = 0; mi < 2; ++mi) {
        int row = wm * 32 + mi * 16 + (lane & 15);
        aRow[mi] = (uint32_t)(row * 128);
        aXor[mi] = (uint32_t)((row & 7) * 16);
    }
    const uint32_t aK = ((lane >> 4) * 16);

    uint32_t bRow[4], bXor[4];
#pragma unroll
    for (int g = 0; g < 4; ++g) {
        int row = wn * 64 + g * 16 + ((lane >> 4) << 3) + (lane & 7);
        bRow[g] = (uint32_t)(row * 128);
        bXor[g] = (uint32_t)((row & 7) * 16);
    }
    const uint32_t bK = (((lane >> 3) & 1) * 16);

    float acc[2][8][4];
#pragma unroll
    for (int mi = 0; mi < 2; ++mi)
#pragma unroll
        for (int ni = 0; ni < 8; ++ni)
#pragma unroll
            for (int r = 0; r < 4; ++r) acc[mi][ni][r] = 0.0f;

    for (int it = 0; it < KITERS; ++it) {
        const int buf = it & 1;
        __syncthreads();                         // barrier 1 (data visible)

        const uint32_t abase = S + A_OFF + buf * A_STAGE;
        const uint32_t bbase = S + B_OFF + buf * B_STAGE;
#pragma unroll
        for (int kk = 0; kk < 4; ++kk) {
            uint32_t a[2][4];
#pragma unroll
            for (int mi = 0; mi < 2; ++mi)
                LDSM_X4(a[mi][0], a[mi][1], a[mi][2], a[mi][3],
                        abase + aRow[mi] + (((uint32_t)(kk * 32) + aK) ^ aXor[mi]));
            uint32_t b[4][4];
#pragma unroll
            for (int g = 0; g < 4; ++g)
                LDSM_X4(b[g][0], b[g][1], b[g][2], b[g][3],
                        bbase + bRow[g] + (((uint32_t)(kk * 32) + bK) ^ bXor[g]));
#pragma unroll
            for (int mi = 0; mi < 2; ++mi)
#pragma unroll
                for (int g = 0; g < 4; ++g) {
                    MMA16816(acc[mi][2 * g + 0], a[mi], b[g][0], b[g][1]);
                    MMA16816(acc[mi][2 * g + 1], a[mi], b[g][2], b[g][3]);
                }
        }

        if (it + 2 < KITERS) __syncthreads();    // barrier 2 (buf drained)
    }

    // ---- epilogue (MMA warps only) ----
    const int r  = lane >> 2;
    const int c2 = (lane & 3) * 2;
    float bia[8][2];
#pragma unroll
    for (int ni = 0; ni < 8; ++ni) {
        bia[ni][0] = __ldg(&bias[n0 + wn * 64 + ni * 8 + c2 + 0]);
        bia[ni][1] = __ldg(&bias[n0 + wn * 64 + ni * 8 + c2 + 1]);
    }
#pragma unroll
    for (int mi = 0; mi < 2; ++mi) {
        const int mrow = m0 + wm * 32 + mi * 16 + r;
        float* o0 = out + (size_t)mrow * OUT_DIM + n0 + wn * 64;
        float* o1 = o0 + 8 * OUT_DIM;
#pragma unroll
        for (int ni = 0; ni < 8; ++ni) {
            const int nc = ni * 8 + c2;
            float2 v0 = {acc[mi][ni][0] + bia[ni][0], acc[mi][ni][1] + bia[ni][1]};
            float2 v1 = {acc[mi][ni][2] + bia[ni][0], acc[mi][ni][3] + bia[ni][1]};
            *reinterpret_cast<float2*>(o0 + nc) = v0;
            *reinterpret_cast<float2*>(o1 + nc) = v1;
        }
    }
}

// ---------------- launch ----------------
extern "C" void kernel_launch(void* const* d_in, const int* in_sizes, int n_in,
                              void* d_out, int out_size) {
    const float* x     = (const float*)d_in[0];
    const float* sw    = (const float*)d_in[1];
    const float* W     = (const float*)d_in[2];
    const float* bias  = (const float*)d_in[3];
    const float* knots = (const float*)d_in[4];
    float* out = (float*)d_out;

    build_prep_kernel<<<A_BLOCKS + B_BLOCKS, 256>>>(x, sw, W);

    cudaFuncSetAttribute(kan_gemm_kernel, cudaFuncAttributeMaxDynamicSharedMemorySize, SMEM_BYTES);
    dim3 grid(OUT_DIM / BN, BATCH / BM);   // (8, 128) = 1024 CTAs
    kan_gemm_kernel<<<grid, THREADS, SMEM_BYTES>>>(out, bias, knots);
}